// round 16
// baseline (speedup 1.0000x reference)
#include <cuda_runtime.h>

// SqueezeSeg Recurrent CRF — per-iteration kernel chain, sm_103a. Round 8.
// B=16, C=4, H=64, W=512, 3x5 neighborhood (14 neighbors), 3 iterations.
//
// R8 = R7 + deeper vertical register blocking (4 H-pixels per thread):
//  - 4 vertically-adjacent pixels share 6 stencil rows: 30 cells per 4 px
//    (15 LDS-pairs/px vs 20 in R7), each cell consumed by up to 3 pixels
//    with compile-time dz -> weight/bf-plane selection.
//  - TH=16 tile: halo cells drop to 19.5% of outputs (was 33%).
//  - 4 independent accumulator chains -> more ILP for LDS/LDG latency.
//  - Interleaved softmaxed-unary handoff between iterations ([B,H,W,4]
//    float4); softmax computed once per pixel in the producing kernel.
//  - Packed fma.rn.f32x2 stencil accumulation.
//
// Math notes (verified vs reference):
//  - ANG_THETA_A == BILATERAL_THETA_A => g_ang == g_bi => bi_ang == ang.
//  - compat = ones - eye => out[o] = unary[o] + 0.02*(sum_ang - ang[o])
//                                   + 0.10*(sum_bi - bi[o]).

#define BATCH 16
#define NC 4
#define HH 64
#define WW 512
#define PLANE (HH*WW)

#define TH 16         // tile height
#define TW 64         // tile width
#define TYN 4         // threads in y; each covers 4 rows
#define PXT 4         // pixels per thread (vertical)
#define SH (TH + 2)   // 18
#define SW (TW + 4)   // 68
#define NTH (TW * TYN)   // 256

typedef unsigned long long u64t;

__device__ __forceinline__ u64t ffma2(u64t a, u64t b, u64t c) {
    u64t d;
    asm("fma.rn.f32x2 %0, %1, %2, %3;" : "=l"(d) : "l"(a), "l"(b), "l"(c));
    return d;
}
__device__ __forceinline__ u64t pack2(float lo, float hi) {
    u64t d;
    asm("mov.b64 %0, {%1, %2};" : "=l"(d) : "f"(lo), "f"(hi));
    return d;
}
__device__ __forceinline__ void unpack2(u64t v, float& lo, float& hi) {
    asm("mov.b64 {%0, %1}, %2;" : "=f"(lo), "=f"(hi) : "l"(v));
}

// interleaved softmaxed-unary scratch: [B,H,W] of float4
__device__ float4 g_uA[BATCH * PLANE];
__device__ float4 g_uB[BATCH * PLANE];

template<bool OUT_PLANAR>
__device__ __forceinline__ void write_px(
    float* __restrict__ xout, int b, int off,
    u64t ang_lo, u64t ang_hi, u64t cond_lo, u64t cond_hi,
    float mc, float4 uc)
{
    float a0, a1, a2, a3, c0, c1, c2, c3;
    unpack2(ang_lo,  a0, a1);
    unpack2(ang_hi,  a2, a3);
    unpack2(cond_lo, c0, c1);
    unpack2(cond_hi, c2, c3);

    const float b0 = c0 * mc * a0;     // bi_ang == ang (equal thetas)
    const float b1 = c1 * mc * a1;
    const float b2 = c2 * mc * a2;
    const float b3 = c3 * mc * a3;
    const float sa = a0 + a1 + a2 + a3;
    const float sb = b0 + b1 + b2 + b3;

    const float o0 = uc.x + 0.02f * (sa - a0) + 0.10f * (sb - b0);
    const float o1 = uc.y + 0.02f * (sa - a1) + 0.10f * (sb - b1);
    const float o2 = uc.z + 0.02f * (sa - a2) + 0.10f * (sb - b2);
    const float o3 = uc.w + 0.02f * (sa - a3) + 0.10f * (sb - b3);

    if (OUT_PLANAR) {
        float* ob = xout + (size_t)b * NC * PLANE;
        ob[0 * PLANE + off] = o0;
        ob[1 * PLANE + off] = o1;
        ob[2 * PLANE + off] = o2;
        ob[3 * PLANE + off] = o3;
    } else {
        const float mx = fmaxf(fmaxf(o0, o1), fmaxf(o2, o3));
        float u0 = __expf(o0 - mx);
        float u1 = __expf(o1 - mx);
        float u2 = __expf(o2 - mx);
        float u3 = __expf(o3 - mx);
        const float inv = 1.0f / (u0 + u1 + u2 + u3);
        float4* ub = (float4*)xout + (size_t)b * PLANE;
        ub[off] = make_float4(u0 * inv, u1 * inv, u2 * inv, u3 * inv);
    }
}

// IN_PLANAR:  input raw planar x [B,4,H,W] (softmax in phase 1);
//             else interleaved softmaxed u [B,H,W,4].
// OUT_PLANAR: output raw planar x' (final); else softmax(x') interleaved.
template<bool IN_PLANAR, bool OUT_PLANAR>
__global__ __launch_bounds__(NTH)
void crf_iter_kernel(const float* __restrict__ xin,
                     const float* __restrict__ bf,      // [B,14,H,W]
                     const float* __restrict__ mask,    // [B,H,W]
                     float* __restrict__ xout)
{
    __shared__ float4 s_u[SH][SW];
    __shared__ float  s_m[SH][SW];

    const int b  = blockIdx.z;
    const int h0 = blockIdx.y * TH;
    const int w0 = blockIdx.x * TW;
    const int tx = threadIdx.x;   // 0..63 along W
    const int ty = threadIdx.y;   // 0..3 -> rows 4ty..4ty+3
    const int tid = ty * TW + tx;

    const float* mb = mask + (size_t)b * PLANE;

    // ---- Phase 1: load unary region into smem (tile + halo)
    #pragma unroll
    for (int i = tid; i < SH * SW; i += NTH) {
        const int sh = i / SW;
        const int sw = i % SW;
        const int h = h0 + sh - 1;
        const int w = w0 + sw - 2;
        float4 u = make_float4(0.f, 0.f, 0.f, 0.f);
        float m = 0.f;
        if (h >= 0 && h < HH && w >= 0 && w < WW) {
            const int off = h * WW + w;
            if (IN_PLANAR) {
                const float* xb = xin + (size_t)b * NC * PLANE;
                const float a0 = xb[0 * PLANE + off];
                const float a1 = xb[1 * PLANE + off];
                const float a2 = xb[2 * PLANE + off];
                const float a3 = xb[3 * PLANE + off];
                const float mx = fmaxf(fmaxf(a0, a1), fmaxf(a2, a3));
                u.x = __expf(a0 - mx);
                u.y = __expf(a1 - mx);
                u.z = __expf(a2 - mx);
                u.w = __expf(a3 - mx);
                const float inv = 1.0f / (u.x + u.y + u.z + u.w);
                u.x *= inv; u.y *= inv; u.z *= inv; u.w *= inv;
            } else {
                const float4* ub = (const float4*)xin + (size_t)b * PLANE;
                u = ub[off];
            }
            m = mb[off];
        }
        s_u[sh][sw] = u;
        s_m[sh][sw] = m;
    }
    __syncthreads();

    // ---- Phase 2: stencil, 4 vertically-adjacent pixels per thread
    // Gaussian weights: d2 in {1,2,4,5}, denom 2*0.9^2 = 1.62
    const float inv_den = 1.0f / 1.62f;
    const float e1 = __expf(-1.0f * inv_den);
    const float e2 = __expf(-2.0f * inv_den);
    const float e4 = __expf(-4.0f * inv_den);
    const float e5 = __expf(-5.0f * inv_den);
    const u64t g2[4] = { pack2(e1, e1), pack2(e2, e2), pack2(e4, e4), pack2(e5, e5) };

    // per-dz weight index into g2 and bf k-plane index (compile-time folded)
    const signed char gidx[3][5] = { {3,1,0,1,3}, {2,0,0,0,2}, {3,1,0,1,3} };
    const signed char ktab[3][5] = { {0,1,2,3,4}, {5,6,0,7,8}, {9,10,11,12,13} };

    const int r0 = PXT * ty;                 // first pixel tile row
    const int offbase = (h0 + r0) * WW + (w0 + tx);
    const float* bfb = bf + (size_t)b * 14 * PLANE;

    // per-pixel bf base pointers (rows r0..r0+3)
    const float* bfq0 = bfb + offbase;
    const float* bfq1 = bfq0 + WW;
    const float* bfq2 = bfq1 + WW;
    const float* bfq3 = bfq2 + WW;

    u64t al[PXT] = {0,0,0,0}, ah[PXT] = {0,0,0,0};
    u64t cl[PXT] = {0,0,0,0}, ch[PXT] = {0,0,0,0};

    #pragma unroll
    for (int s = 0; s < PXT + 2; ++s) {      // smem row = r0 + s
        const int sh = r0 + s;
        #pragma unroll
        for (int j = 0; j < 5; ++j) {
            const ulonglong2 u2 =
                *reinterpret_cast<const ulonglong2*>(&s_u[sh][tx + j]);
            const float m = s_m[sh][tx + j];
            #pragma unroll
            for (int q = 0; q < PXT; ++q) {
                const int dz = s - q;
                if (dz < 0 || dz > 2) continue;
                if (dz == 1 && j == 2) continue;   // center excluded
                const u64t g = g2[(int)gidx[dz][j]];
                al[q] = ffma2(g, u2.x, al[q]);
                ah[q] = ffma2(g, u2.y, ah[q]);
                const float* bfq = (q == 0) ? bfq0 : (q == 1) ? bfq1
                                 : (q == 2) ? bfq2 : bfq3;
                const float bm = bfq[(int)ktab[dz][j] * PLANE] * m;
                const u64t bm2 = pack2(bm, bm);
                cl[q] = ffma2(bm2, u2.x, cl[q]);
                ch[q] = ffma2(bm2, u2.y, ch[q]);
            }
        }
    }

    // ---- Epilogue: all 4 pixels
    #pragma unroll
    for (int q = 0; q < PXT; ++q) {
        const float  mc = s_m[r0 + q + 1][tx + 2];
        const float4 uc = s_u[r0 + q + 1][tx + 2];
        write_px<OUT_PLANAR>(xout, b, offbase + q * WW,
                             al[q], ah[q], cl[q], ch[q], mc, uc);
    }
}

extern "C" void kernel_launch(void* const* d_in, const int* in_sizes, int n_in,
                              void* d_out, int out_size)
{
    const float* x    = (const float*)d_in[0];  // [16,4,64,512]
    const float* bf   = (const float*)d_in[1];  // [16,1,14,64,512]
    const float* mask = (const float*)d_in[2];  // [16,1,64,512]
    float* out = (float*)d_out;

    float4* ua = nullptr;
    float4* ub = nullptr;
    cudaGetSymbolAddress((void**)&ua, g_uA);
    cudaGetSymbolAddress((void**)&ub, g_uB);

    dim3 block(TW, TYN, 1);                 // 256 threads, 4 px/thread (H)
    dim3 grid(WW / TW, HH / TH, BATCH);     // 8 x 4 x 16 = 512 blocks

    crf_iter_kernel<true,  false><<<grid, block>>>(x,          bf, mask, (float*)ua);
    crf_iter_kernel<false, false><<<grid, block>>>((float*)ua, bf, mask, (float*)ub);
    crf_iter_kernel<false, true ><<<grid, block>>>((float*)ub, bf, mask, out);
}

// round 17
// speedup vs baseline: 1.5126x; 1.5126x over previous
#include <cuda_runtime.h>

// SqueezeSeg Recurrent CRF — per-iteration kernel chain, sm_103a. Round 9.
// B=16, C=4, H=64, W=512, 3x5 neighborhood (14 neighbors), 3 iterations.
//
// R9 = R7 (best: 28.48us) + explicit bf prefetch across the barrier:
//  - The 28 per-thread bf loads (14 planes x 2 pixels) depend only on
//    indices, not smem. Issue them BEFORE phase-1 + __syncthreads so their
//    L2 latency (~250cyc) overlaps the smem fill/softmax/barrier; the
//    post-barrier tap chain then runs from registers (LDS-only stalls).
//  - launch_bounds(256,3): reg cap 85 (R7's (256,5) would clamp to 51 and
//    spill the prefetch registers).
//  - Everything else identical to R7: 2 vertical px/thread, shared stencil
//    rows, interleaved softmaxed-u handoff, packed fma.rn.f32x2.
//
// Math notes (verified vs reference):
//  - ANG_THETA_A == BILATERAL_THETA_A => g_ang == g_bi => bi_ang == ang.
//  - compat = ones - eye => out[o] = unary[o] + 0.02*(sum_ang - ang[o])
//                                   + 0.10*(sum_bi - bi[o]).

#define BATCH 16
#define NC 4
#define HH 64
#define WW 512
#define PLANE (HH*WW)

#define TH 8          // tile height
#define TW 64         // tile width
#define TYN 4         // threads in y; each covers 2 rows
#define SH (TH + 2)
#define SW (TW + 4)
#define NTH (TW * TYN)   // 256

typedef unsigned long long u64t;

__device__ __forceinline__ u64t ffma2(u64t a, u64t b, u64t c) {
    u64t d;
    asm("fma.rn.f32x2 %0, %1, %2, %3;" : "=l"(d) : "l"(a), "l"(b), "l"(c));
    return d;
}
__device__ __forceinline__ u64t pack2(float lo, float hi) {
    u64t d;
    asm("mov.b64 %0, {%1, %2};" : "=l"(d) : "f"(lo), "f"(hi));
    return d;
}
__device__ __forceinline__ void unpack2(u64t v, float& lo, float& hi) {
    asm("mov.b64 {%0, %1}, %2;" : "=f"(lo), "=f"(hi) : "l"(v));
}

// interleaved softmaxed-unary scratch: [B,H,W] of float4
__device__ float4 g_uA[BATCH * PLANE];
__device__ float4 g_uB[BATCH * PLANE];

template<bool OUT_PLANAR>
__device__ __forceinline__ void write_px(
    float* __restrict__ xout, int b, int off,
    u64t ang_lo, u64t ang_hi, u64t cond_lo, u64t cond_hi,
    float mc, float4 uc)
{
    float a0, a1, a2, a3, c0, c1, c2, c3;
    unpack2(ang_lo,  a0, a1);
    unpack2(ang_hi,  a2, a3);
    unpack2(cond_lo, c0, c1);
    unpack2(cond_hi, c2, c3);

    const float b0 = c0 * mc * a0;     // bi_ang == ang (equal thetas)
    const float b1 = c1 * mc * a1;
    const float b2 = c2 * mc * a2;
    const float b3 = c3 * mc * a3;
    const float sa = a0 + a1 + a2 + a3;
    const float sb = b0 + b1 + b2 + b3;

    const float o0 = uc.x + 0.02f * (sa - a0) + 0.10f * (sb - b0);
    const float o1 = uc.y + 0.02f * (sa - a1) + 0.10f * (sb - b1);
    const float o2 = uc.z + 0.02f * (sa - a2) + 0.10f * (sb - b2);
    const float o3 = uc.w + 0.02f * (sa - a3) + 0.10f * (sb - b3);

    if (OUT_PLANAR) {
        float* ob = xout + (size_t)b * NC * PLANE;
        ob[0 * PLANE + off] = o0;
        ob[1 * PLANE + off] = o1;
        ob[2 * PLANE + off] = o2;
        ob[3 * PLANE + off] = o3;
    } else {
        const float mx = fmaxf(fmaxf(o0, o1), fmaxf(o2, o3));
        float u0 = __expf(o0 - mx);
        float u1 = __expf(o1 - mx);
        float u2 = __expf(o2 - mx);
        float u3 = __expf(o3 - mx);
        const float inv = 1.0f / (u0 + u1 + u2 + u3);
        float4* ub = (float4*)xout + (size_t)b * PLANE;
        ub[off] = make_float4(u0 * inv, u1 * inv, u2 * inv, u3 * inv);
    }
}

// IN_PLANAR:  input raw planar x [B,4,H,W] (softmax in phase 1);
//             else interleaved softmaxed u [B,H,W,4].
// OUT_PLANAR: output raw planar x' (final); else softmax(x') interleaved.
template<bool IN_PLANAR, bool OUT_PLANAR>
__global__ __launch_bounds__(NTH, 3)
void crf_iter_kernel(const float* __restrict__ xin,
                     const float* __restrict__ bf,      // [B,14,H,W]
                     const float* __restrict__ mask,    // [B,H,W]
                     float* __restrict__ xout)
{
    __shared__ float4 s_u[SH][SW];
    __shared__ float  s_m[SH][SW];

    const int b  = blockIdx.z;
    const int h0 = blockIdx.y * TH;
    const int w0 = blockIdx.x * TW;
    const int tx = threadIdx.x;   // 0..63 along W
    const int ty = threadIdx.y;   // 0..3 -> rows 2ty, 2ty+1
    const int tid = ty * TW + tx;

    // ---- Prefetch: 28 bf loads issued BEFORE the smem phase + barrier.
    // Their L2 latency overlaps the entire phase-1 fill.
    const int r0   = 2 * ty;
    const int off0 = (h0 + r0) * WW + (w0 + tx);
    const int off1 = off0 + WW;
    const float* bfb = bf + (size_t)b * 14 * PLANE;
    const float* bf0 = bfb + off0;
    const float* bf1 = bfb + off1;

    float pf0[14], pf1[14];
    #pragma unroll
    for (int k = 0; k < 14; ++k) pf0[k] = __ldg(bf0 + k * PLANE);
    #pragma unroll
    for (int k = 0; k < 14; ++k) pf1[k] = __ldg(bf1 + k * PLANE);

    const float* mb = mask + (size_t)b * PLANE;

    // ---- Phase 1: load unary region into smem (tile+halo)
    #pragma unroll
    for (int i = tid; i < SH * SW; i += NTH) {
        const int sh = i / SW;
        const int sw = i % SW;
        const int h = h0 + sh - 1;
        const int w = w0 + sw - 2;
        float4 u = make_float4(0.f, 0.f, 0.f, 0.f);
        float m = 0.f;
        if (h >= 0 && h < HH && w >= 0 && w < WW) {
            const int off = h * WW + w;
            if (IN_PLANAR) {
                const float* xb = xin + (size_t)b * NC * PLANE;
                const float a0 = xb[0 * PLANE + off];
                const float a1 = xb[1 * PLANE + off];
                const float a2 = xb[2 * PLANE + off];
                const float a3 = xb[3 * PLANE + off];
                const float mx = fmaxf(fmaxf(a0, a1), fmaxf(a2, a3));
                u.x = __expf(a0 - mx);
                u.y = __expf(a1 - mx);
                u.z = __expf(a2 - mx);
                u.w = __expf(a3 - mx);
                const float inv = 1.0f / (u.x + u.y + u.z + u.w);
                u.x *= inv; u.y *= inv; u.z *= inv; u.w *= inv;
            } else {
                const float4* ub = (const float4*)xin + (size_t)b * PLANE;
                u = ub[off];
            }
            m = mb[off];
        }
        s_u[sh][sw] = u;
        s_m[sh][sw] = m;
    }
    __syncthreads();

    // ---- Phase 2: stencil, 2 vertically-adjacent pixels per thread
    // Gaussian weights: d2 in {1,2,4,5}, denom 2*0.9^2 = 1.62
    const float inv_den = 1.0f / 1.62f;
    const float e1 = __expf(-1.0f * inv_den);
    const float e2 = __expf(-2.0f * inv_den);
    const float e4 = __expf(-4.0f * inv_den);
    const float e5 = __expf(-5.0f * inv_den);
    const u64t g2[4] = { pack2(e1, e1), pack2(e2, e2), pack2(e4, e4), pack2(e5, e5) };

    // per-dz weight index into g2 and bf k-plane index (compile-time folded)
    const signed char gidx[3][5] = { {3,1,0,1,3}, {2,0,0,0,2}, {3,1,0,1,3} };
    const signed char ktab[3][5] = { {0,1,2,3,4}, {5,6,0,7,8}, {9,10,11,12,13} };

    u64t a0l = 0, a0h = 0, c0l = 0, c0h = 0;   // px0 ang/cond (class pairs)
    u64t a1l = 0, a1h = 0, c1l = 0, c1h = 0;   // px1

    #pragma unroll
    for (int s = 0; s < 4; ++s) {              // smem row = r0 + s
        const int sh = r0 + s;
        #pragma unroll
        for (int j = 0; j < 5; ++j) {
            const ulonglong2 u2 =
                *reinterpret_cast<const ulonglong2*>(&s_u[sh][tx + j]);
            const float m = s_m[sh][tx + j];
            if (s <= 2 && !(s == 1 && j == 2)) {       // px0 tap, dz = s
                const u64t g = g2[(int)gidx[s][j]];
                a0l = ffma2(g, u2.x, a0l);
                a0h = ffma2(g, u2.y, a0h);
                const float bm = pf0[(int)ktab[s][j]] * m;
                const u64t bm2 = pack2(bm, bm);
                c0l = ffma2(bm2, u2.x, c0l);
                c0h = ffma2(bm2, u2.y, c0h);
            }
            if (s >= 1 && !(s == 2 && j == 2)) {       // px1 tap, dz = s-1
                const u64t g = g2[(int)gidx[s - 1][j]];
                a1l = ffma2(g, u2.x, a1l);
                a1h = ffma2(g, u2.y, a1h);
                const float bm = pf1[(int)ktab[s - 1][j]] * m;
                const u64t bm2 = pack2(bm, bm);
                c1l = ffma2(bm2, u2.x, c1l);
                c1h = ffma2(bm2, u2.y, c1h);
            }
        }
    }

    // ---- Epilogue: both pixels
    const float  mc0 = s_m[r0 + 1][tx + 2];
    const float  mc1 = s_m[r0 + 2][tx + 2];
    const float4 uc0 = s_u[r0 + 1][tx + 2];
    const float4 uc1 = s_u[r0 + 2][tx + 2];

    write_px<OUT_PLANAR>(xout, b, off0, a0l, a0h, c0l, c0h, mc0, uc0);
    write_px<OUT_PLANAR>(xout, b, off1, a1l, a1h, c1l, c1h, mc1, uc1);
}

extern "C" void kernel_launch(void* const* d_in, const int* in_sizes, int n_in,
                              void* d_out, int out_size)
{
    const float* x    = (const float*)d_in[0];  // [16,4,64,512]
    const float* bf   = (const float*)d_in[1];  // [16,1,14,64,512]
    const float* mask = (const float*)d_in[2];  // [16,1,64,512]
    float* out = (float*)d_out;

    float4* ua = nullptr;
    float4* ub = nullptr;
    cudaGetSymbolAddress((void**)&ua, g_uA);
    cudaGetSymbolAddress((void**)&ub, g_uB);

    dim3 block(TW, TYN, 1);                 // 256 threads, 2 px/thread (H)
    dim3 grid(WW / TW, HH / TH, BATCH);     // 8 x 8 x 16 = 1024 blocks

    crf_iter_kernel<true,  false><<<grid, block>>>(x,          bf, mask, (float*)ua);
    crf_iter_kernel<false, false><<<grid, block>>>((float*)ua, bf, mask, (float*)ub);
    crf_iter_kernel<false, true ><<<grid, block>>>((float*)ub, bf, mask, out);
}